// round 1
// baseline (speedup 1.0000x reference)
#include <cuda_runtime.h>
#include <math.h>

// ---------------- problem constants ----------------
#define NB   16
#define DIM  64
#define DLEN 64
#define PLEN 1200
#define D1L  61
#define D2L  56
#define D3L  49
#define P1L  1197
#define P2L  1190
#define P3L  1179
#define C1   40
#define C2   80
#define C3   160

// ---------------- scratch (device globals; no allocs allowed) ----------------
__device__ float g_de[NB * DIM * DLEN];
__device__ float g_pe[NB * DIM * PLEN];
__device__ float g_d1[NB * C1 * D1L];
__device__ float g_d2[NB * C2 * D2L];
__device__ float g_dc[NB * C3 * D3L];
__device__ float g_p1[NB * C1 * P1L];
__device__ float g_p2[NB * C2 * P2L];
__device__ float g_pc[NB * C3 * P3L];
__device__ float g_datt[NB * C3 * D3L];   // [b][k][d]
__device__ float g_patt[NB * C3 * P3L];   // [b][k][p]
__device__ float g_Sd[NB * C3 * D3L];
__device__ float g_Sp[NB * C3 * P3L];
__device__ float g_catte[NB * C3 * D3L];  // sigmoid attention, [b][k][d]
__device__ float g_patte[NB * C3 * P3L];
__device__ float g_pair[NB * 320];
__device__ float g_h1[NB * 1024];
__device__ float g_h2[NB * 1024];
__device__ float g_h3[NB * 512];

// ---------------- kernels ----------------

// out[b][c][l] = emb[tok[b][l]][c]   (C fixed = 64)
__global__ void embed_kernel(const int* __restrict__ tok, const float* __restrict__ emb,
                             float* __restrict__ out, int L)
{
    int b = blockIdx.y;
    int idx = blockIdx.x * blockDim.x + threadIdx.x;
    if (idx >= 64 * L) return;
    int c = idx / L, l = idx - c * L;
    out[((size_t)b * 64 + c) * L + l] = emb[tok[b * L + l] * 64 + c];
}

// out[b][o][l] = relu(bias[o] + sum_{i,k} in[b][i][l+k] * W[o][i][k])
// grid: (ceil(Lout/(blockDim*4)), Cout, B). Each thread computes 4 l-positions.
template <int K, int CIN>
__global__ void conv_relu_kernel(const float* __restrict__ in, const float* __restrict__ W,
                                 const float* __restrict__ bias, float* __restrict__ out,
                                 int Lin, int Lout, int Cout)
{
    __shared__ float ws[CIN * K];
    const int o = blockIdx.y, b = blockIdx.z;
    for (int i = threadIdx.x; i < CIN * K; i += blockDim.x)
        ws[i] = W[(size_t)o * CIN * K + i];
    __syncthreads();

    const int T = 4;
    int l0 = (blockIdx.x * blockDim.x + threadIdx.x) * T;
    if (l0 >= Lout) return;

    float bv = bias[o];
    float acc[T];
#pragma unroll
    for (int t = 0; t < T; t++) acc[t] = bv;

    const float* inb = in + (size_t)b * CIN * Lin;
#pragma unroll 1
    for (int i = 0; i < CIN; i++) {
        const float* row = inb + (size_t)i * Lin + l0;
        float win[T + K - 1];
#pragma unroll
        for (int j = 0; j < T + K - 1; j++)
            win[j] = (l0 + j < Lin) ? row[j] : 0.f;
#pragma unroll
        for (int k = 0; k < K; k++) {
            float w = ws[i * K + k];
#pragma unroll
            for (int t = 0; t < T; t++)
                acc[t] = fmaf(w, win[k + t], acc[t]);
        }
    }
    float* op = out + ((size_t)b * Cout + o) * Lout + l0;
#pragma unroll
    for (int t = 0; t < T; t++)
        if (l0 + t < Lout) op[t] = fmaxf(acc[t], 0.f);
}

// y[b][o][l] = bias[o] + sum_c W[o][c] * x[b][c][l]    (C = 160, O = 160)
__global__ void proj_kernel(const float* __restrict__ x, const float* __restrict__ W,
                            const float* __restrict__ bias, float* __restrict__ y,
                            int C, int L, int O)
{
    int b = blockIdx.z, o = blockIdx.y;
    int l = blockIdx.x * blockDim.x + threadIdx.x;
    if (l >= L) return;
    const float* xb = x + (size_t)b * C * L + l;
    const float* Wo = W + (size_t)o * C;
    float acc = bias[o];
#pragma unroll 4
    for (int c = 0; c < C; c++)
        acc = fmaf(Wo[c], xb[(size_t)c * L], acc);
    y[((size_t)b * O + o) * L + l] = acc;
}

// For each (b,k): S_d[d] = sum_p relu(dv[d]+pv[p]), S_p[p] = sum_d relu(dv[d]+pv[p]).
// Deterministic (shuffle + smem tree reduce, no atomics). grid (160, NB), block 256.
__global__ void interact_kernel(const float* __restrict__ datt, const float* __restrict__ patt,
                                float* __restrict__ Sd, float* __restrict__ Sp)
{
    int k = blockIdx.x, b = blockIdx.y;
    int t = threadIdx.x;
    __shared__ float dvs[D3L];
    __shared__ float red[8][D3L];

    const float* dv = datt + ((size_t)b * C3 + k) * D3L;
    const float* pv = patt + ((size_t)b * C3 + k) * P3L;
    float* SpRow = Sp + ((size_t)b * C3 + k) * P3L;

    if (t < D3L) dvs[t] = dv[t];
    __syncthreads();

    float dl[D3L];
#pragma unroll
    for (int d = 0; d < D3L; d++) dl[d] = dvs[d];
    float sdp[D3L];
#pragma unroll
    for (int d = 0; d < D3L; d++) sdp[d] = 0.f;

    for (int p = t; p < P3L; p += 256) {
        float pvv = pv[p];
        float sp = 0.f;
#pragma unroll
        for (int d = 0; d < D3L; d++) {
            float v = fmaxf(dl[d] + pvv, 0.f);
            sdp[d] += v;
            sp += v;
        }
        SpRow[p] = sp;
    }

    int warp = t >> 5, lane = t & 31;
#pragma unroll
    for (int d = 0; d < D3L; d++) {
        float v = sdp[d];
        v += __shfl_xor_sync(0xffffffffu, v, 16);
        v += __shfl_xor_sync(0xffffffffu, v, 8);
        v += __shfl_xor_sync(0xffffffffu, v, 4);
        v += __shfl_xor_sync(0xffffffffu, v, 2);
        v += __shfl_xor_sync(0xffffffffu, v, 1);
        if (lane == 0) red[warp][d] = v;
    }
    __syncthreads();
    if (t < D3L) {
        float s = 0.f;
#pragma unroll
        for (int w = 0; w < 8; w++) s += red[w][t];
        Sd[((size_t)b * C3 + k) * D3L + t] = s;
    }
}

// out[b][o][l] = sigmoid(invN * sum_k attW[o][k]*S[b][k][l] + attb[o])
__global__ void att_out_kernel(const float* __restrict__ S, const float* __restrict__ Wt,
                               const float* __restrict__ bias, float* __restrict__ out,
                               int L, float invN)
{
    int b = blockIdx.z, o = blockIdx.y;
    int l = blockIdx.x * blockDim.x + threadIdx.x;
    if (l >= L) return;
    const float* Sb = S + (size_t)b * C3 * L + l;
    const float* Wo = Wt + (size_t)o * C3;
    float acc = 0.f;
#pragma unroll 4
    for (int k = 0; k < C3; k++)
        acc = fmaf(Wo[k], Sb[(size_t)k * L], acc);
    acc = fmaf(acc, invN, bias[o]);
    out[((size_t)b * C3 + o) * L + l] = 1.f / (1.f + __expf(-acc));
}

// pair[b][off+k] = max_l x[b][k][l] * (0.5 + att[b][k][l]); one warp per (b,k)
__global__ void pool_kernel(const float* __restrict__ x, const float* __restrict__ att,
                            float* __restrict__ pairv, int L, int off)
{
    int k = blockIdx.x, b = blockIdx.y;
    const float* xr = x + ((size_t)b * C3 + k) * L;
    const float* ar = att + ((size_t)b * C3 + k) * L;
    float m = -1e30f;
    for (int l = threadIdx.x; l < L; l += 32)
        m = fmaxf(m, xr[l] * (0.5f + ar[l]));
#pragma unroll
    for (int s = 16; s; s >>= 1)
        m = fmaxf(m, __shfl_xor_sync(0xffffffffu, m, s));
    if (threadIdx.x == 0) pairv[b * 320 + off + k] = m;
}

// y[b][o] = act(bias[o] + x[b][:] . W[o][:]) ; leaky_relu(0.01) if leaky
__global__ void fc_kernel(const float* __restrict__ x, const float* __restrict__ W,
                          const float* __restrict__ bias, float* __restrict__ y,
                          int IN, int OUT, int leaky)
{
    int b = blockIdx.y;
    int o = blockIdx.x * blockDim.x + threadIdx.x;
    if (o >= OUT) return;
    const float4* xb = (const float4*)(x + (size_t)b * IN);
    const float4* Wo = (const float4*)(W + (size_t)o * IN);
    float acc = bias[o];
    int n4 = IN >> 2;
#pragma unroll 4
    for (int i = 0; i < n4; i++) {
        float4 xv = xb[i], wv = Wo[i];
        acc = fmaf(wv.x, xv.x, acc);
        acc = fmaf(wv.y, xv.y, acc);
        acc = fmaf(wv.z, xv.z, acc);
        acc = fmaf(wv.w, xv.w, acc);
    }
    if (leaky) acc = acc > 0.f ? acc : 0.01f * acc;
    y[(size_t)b * OUT + o] = acc;
}

// ---------------- launch ----------------
extern "C" void kernel_launch(void* const* d_in, const int* in_sizes, int n_in,
                              void* d_out, int out_size)
{
    const int*   dtok = (const int*)d_in[0];
    const int*   ptok = (const int*)d_in[1];
    const float* demb = (const float*)d_in[2];
    const float* pemb = (const float*)d_in[3];
    const float* dW1 = (const float*)d_in[4],  *db1 = (const float*)d_in[5];
    const float* dW2 = (const float*)d_in[6],  *db2 = (const float*)d_in[7];
    const float* dW3 = (const float*)d_in[8],  *db3 = (const float*)d_in[9];
    const float* pW1 = (const float*)d_in[10], *pb1 = (const float*)d_in[11];
    const float* pW2 = (const float*)d_in[12], *pb2 = (const float*)d_in[13];
    const float* pW3 = (const float*)d_in[14], *pb3 = (const float*)d_in[15];
    const float* dattW = (const float*)d_in[16], *dattb = (const float*)d_in[17];
    const float* pattW = (const float*)d_in[18], *pattb = (const float*)d_in[19];
    const float* attW  = (const float*)d_in[20], *attb  = (const float*)d_in[21];
    const float* fc1W = (const float*)d_in[22], *fc1b = (const float*)d_in[23];
    const float* fc2W = (const float*)d_in[24], *fc2b = (const float*)d_in[25];
    const float* fc3W = (const float*)d_in[26], *fc3b = (const float*)d_in[27];
    const float* outW = (const float*)d_in[28], *outb = (const float*)d_in[29];
    float* out = (float*)d_out;

    float *de, *pe, *d1, *d2, *dc, *p1, *p2, *pc;
    float *datt, *patt, *Sd, *Sp, *catte, *patte, *pairv, *h1, *h2, *h3;
    cudaGetSymbolAddress((void**)&de, g_de);
    cudaGetSymbolAddress((void**)&pe, g_pe);
    cudaGetSymbolAddress((void**)&d1, g_d1);
    cudaGetSymbolAddress((void**)&d2, g_d2);
    cudaGetSymbolAddress((void**)&dc, g_dc);
    cudaGetSymbolAddress((void**)&p1, g_p1);
    cudaGetSymbolAddress((void**)&p2, g_p2);
    cudaGetSymbolAddress((void**)&pc, g_pc);
    cudaGetSymbolAddress((void**)&datt, g_datt);
    cudaGetSymbolAddress((void**)&patt, g_patt);
    cudaGetSymbolAddress((void**)&Sd, g_Sd);
    cudaGetSymbolAddress((void**)&Sp, g_Sp);
    cudaGetSymbolAddress((void**)&catte, g_catte);
    cudaGetSymbolAddress((void**)&patte, g_patte);
    cudaGetSymbolAddress((void**)&pairv, g_pair);
    cudaGetSymbolAddress((void**)&h1, g_h1);
    cudaGetSymbolAddress((void**)&h2, g_h2);
    cudaGetSymbolAddress((void**)&h3, g_h3);

    // embeddings
    embed_kernel<<<dim3((64 * DLEN + 255) / 256, NB), 256>>>(dtok, demb, de, DLEN);
    embed_kernel<<<dim3((64 * PLEN + 255) / 256, NB), 256>>>(ptok, pemb, pe, PLEN);

    // drug CNN stack
    conv_relu_kernel<4, 64><<<dim3(1, C1, NB), 64>>>(de, dW1, db1, d1, DLEN, D1L, C1);
    conv_relu_kernel<6, 40><<<dim3(1, C2, NB), 64>>>(d1, dW2, db2, d2, D1L, D2L, C2);
    conv_relu_kernel<8, 80><<<dim3(1, C3, NB), 64>>>(d2, dW3, db3, dc, D2L, D3L, C3);

    // protein CNN stack
    conv_relu_kernel<4, 64><<<dim3(3, C1, NB), 128>>>(pe, pW1, pb1, p1, PLEN, P1L, C1);
    conv_relu_kernel<8, 40><<<dim3(3, C2, NB), 128>>>(p1, pW2, pb2, p2, P1L, P2L, C2);
    conv_relu_kernel<12, 80><<<dim3(3, C3, NB), 128>>>(p2, pW3, pb3, pc, P2L, P3L, C3);

    // per-token attention projections: [b][k][len]
    proj_kernel<<<dim3(1, C3, NB), 64>>>(dc, dattW, dattb, datt, C3, D3L, C3);
    proj_kernel<<<dim3((P3L + 255) / 256, C3, NB), 256>>>(pc, pattW, pattb, patt, C3, P3L, C3);

    // interaction sums (mean commuted past the linear attW projection)
    interact_kernel<<<dim3(C3, NB), 256>>>(datt, patt, Sd, Sp);

    // attention outputs: sigmoid((S/N) @ attW^T + attb)
    att_out_kernel<<<dim3(1, C3, NB), 64>>>(Sd, attW, attb, catte, D3L, 1.f / (float)P3L);
    att_out_kernel<<<dim3((P3L + 255) / 256, C3, NB), 256>>>(Sp, attW, attb, patte, P3L, 1.f / (float)D3L);

    // gated global max pool -> pair[b][320]
    pool_kernel<<<dim3(C3, NB), 32>>>(dc, catte, pairv, D3L, 0);
    pool_kernel<<<dim3(C3, NB), 32>>>(pc, patte, pairv, P3L, 160);

    // MLP head
    fc_kernel<<<dim3(4, NB), 256>>>(pairv, fc1W, fc1b, h1, 320, 1024, 1);
    fc_kernel<<<dim3(4, NB), 256>>>(h1, fc2W, fc2b, h2, 1024, 1024, 1);
    fc_kernel<<<dim3(2, NB), 256>>>(h2, fc3W, fc3b, h3, 1024, 512, 1);
    fc_kernel<<<dim3(1, NB), 32>>>(h3, outW, outb, out, 512, 2, 0);
}

// round 2
// speedup vs baseline: 1.9234x; 1.9234x over previous
#include <cuda_runtime.h>
#include <math.h>

// ---------------- problem constants ----------------
#define NB   16
#define DIM  64
#define DLEN 64
#define PLEN 1200
#define D1L  61
#define D2L  56
#define D3L  49
#define P1L  1197
#define P2L  1190
#define P3L  1179
#define C1   40
#define C2   80
#define C3   160

typedef unsigned long long u64;

// ---------------- scratch (device globals; no allocs allowed) ----------------
__device__ float g_de[NB * DIM * DLEN];
__device__ float g_pe[NB * DIM * PLEN];
__device__ float g_d1[NB * C1 * D1L];
__device__ float g_d2[NB * C2 * D2L];
__device__ float g_dc[NB * C3 * D3L];
__device__ float g_p1[NB * C1 * P1L];
__device__ float g_p2[NB * C2 * P2L];
__device__ float g_pc[NB * C3 * P3L];
__device__ float g_datt[NB * C3 * D3L];   // [b][k][d]
__device__ float g_patt[NB * C3 * P3L];   // [b][k][p]
__device__ float g_Sd[NB * C3 * D3L];
__device__ float g_Sp[NB * C3 * P3L];
__device__ float g_catte[NB * C3 * D3L];
__device__ float g_patte[NB * C3 * P3L];
__device__ float g_pair[NB * 320];
__device__ float g_h1[NB * 1024];
__device__ float g_h2[NB * 1024];
__device__ float g_h3[NB * 512];

// ---------------- f32x2 packed helpers ----------------
__device__ __forceinline__ u64 pack2(float lo, float hi) {
    u64 d;
    asm("mov.b64 %0, {%1, %2};" : "=l"(d) : "r"(__float_as_uint(lo)), "r"(__float_as_uint(hi)));
    return d;
}
__device__ __forceinline__ void unpack2(float& lo, float& hi, u64 v) {
    unsigned int a, b;
    asm("mov.b64 {%0, %1}, %2;" : "=r"(a), "=r"(b) : "l"(v));
    lo = __uint_as_float(a); hi = __uint_as_float(b);
}
__device__ __forceinline__ void fma2(u64& d, u64 a, u64 b) {
    asm("fma.rn.f32x2 %0, %1, %2, %3;" : "=l"(d) : "l"(a), "l"(b), "l"(d));
}

// ---------------- generic tiled conv / K=1 GEMM kernel ----------------
// out[b][o][l] = epi( bias[o] + sum_{i,k} in[b][i][l+k] * W[o][i*K+k] )
// EPI: 0 = relu (bias in init), 1 = linear (bias in init),
//      2 = sigmoid(scale*acc + bias)  (bias/scale in epilogue)
// Thread tile: 4 outputs (o) x 4 positions (l), o-dim packed as 2x f32x2.
template <int K, int CIN, int CH, int TILE_L, int TILE_O, int EPI>
__global__ void conv_t(const float* __restrict__ in, const float* __restrict__ W,
                       const float* __restrict__ bias, float* __restrict__ out,
                       int Lin, int Lout, int Cout, float scale)
{
    constexpr int LT   = TILE_L / 4;          // l-lanes
    constexpr int OT   = TILE_O / 4;          // o-groups
    constexpr int NW4  = (K + 6) / 4;         // float4s per window (covers K+3 floats)
    constexpr int PITCH = TILE_L + 4 * NW4;   // smem row pitch (floats, %4==0)
    constexpr int WV   = TILE_L + K - 1;      // valid columns per row
    constexpr int NTHR = LT * OT;

    __shared__ float inS[CH * PITCH];
    __shared__ float wS[CH * K * TILE_O];

    const int b  = blockIdx.z;
    const int o0 = blockIdx.y * TILE_O;
    const int l0 = blockIdx.x * TILE_L;
    const int tid = threadIdx.x;
    const int lx = tid % LT, oy = tid / LT;
    const int lbase = lx * 4;

    u64 accp[2][4];
#pragma unroll
    for (int p = 0; p < 2; p++)
#pragma unroll
        for (int t = 0; t < 4; t++) {
            if (EPI == 2) accp[p][t] = 0ull;
            else accp[p][t] = pack2(bias[o0 + oy * 4 + 2 * p], bias[o0 + oy * 4 + 2 * p + 1]);
        }

    for (int ci0 = 0; ci0 < CIN; ci0 += CH) {
        __syncthreads();
        // stage input slab [CH][WV]
        for (int idx = tid; idx < CH * WV; idx += NTHR) {
            int i2 = idx / WV, j = idx - i2 * WV;
            int gl = l0 + j;
            inS[i2 * PITCH + j] =
                (gl < Lin) ? in[((size_t)b * CIN + (ci0 + i2)) * Lin + gl] : 0.f;
        }
        // stage weights: wS[(i2*K + k)*TILE_O + oo]
        for (int idx = tid; idx < CH * K * TILE_O; idx += NTHR) {
            int oo = idx % TILE_O, rest = idx / TILE_O;
            int i2 = rest / K, k = rest - i2 * K;
            wS[idx] = W[((size_t)(o0 + oo) * CIN + (ci0 + i2)) * K + k];
        }
        __syncthreads();

#pragma unroll 2
        for (int i2 = 0; i2 < CH; i2++) {
            float win[NW4 * 4];
#pragma unroll
            for (int n = 0; n < NW4; n++) {
                float4 v = *(const float4*)&inS[i2 * PITCH + lbase + 4 * n];
                win[4 * n + 0] = v.x; win[4 * n + 1] = v.y;
                win[4 * n + 2] = v.z; win[4 * n + 3] = v.w;
            }
            u64 wdup[K + 3];
#pragma unroll
            for (int j = 0; j < K + 3; j++) wdup[j] = pack2(win[j], win[j]);
#pragma unroll
            for (int k = 0; k < K; k++) {
                const float* wrow = &wS[(i2 * K + k) * TILE_O + oy * 4];
                u64 wp0 = *(const u64*)(wrow);
                u64 wp1 = *(const u64*)(wrow + 2);
#pragma unroll
                for (int t = 0; t < 4; t++) {
                    fma2(accp[0][t], wp0, wdup[k + t]);
                    fma2(accp[1][t], wp1, wdup[k + t]);
                }
            }
        }
    }

    // epilogue + store
#pragma unroll
    for (int p = 0; p < 2; p++) {
        int olo = o0 + oy * 4 + 2 * p;
#pragma unroll
        for (int t = 0; t < 4; t++) {
            int l = l0 + lbase + t;
            if (l >= Lout) continue;
            float vlo, vhi;
            unpack2(vlo, vhi, accp[p][t]);
            if (EPI == 0) { vlo = fmaxf(vlo, 0.f); vhi = fmaxf(vhi, 0.f); }
            else if (EPI == 2) {
                vlo = 1.f / (1.f + __expf(-(vlo * scale + bias[olo])));
                vhi = 1.f / (1.f + __expf(-(vhi * scale + bias[olo + 1])));
            }
            out[((size_t)b * Cout + olo) * Lout + l] = vlo;
            out[((size_t)b * Cout + olo + 1) * Lout + l] = vhi;
        }
    }
}

// ---------------- small kernels ----------------
__global__ void embed_kernel(const int* __restrict__ tok, const float* __restrict__ emb,
                             float* __restrict__ out, int L)
{
    int b = blockIdx.y;
    int idx = blockIdx.x * blockDim.x + threadIdx.x;
    if (idx >= 64 * L) return;
    int c = idx / L, l = idx - c * L;
    out[((size_t)b * 64 + c) * L + l] = emb[tok[b * L + l] * 64 + c];
}

// S_d[d] = sum_p relu(dv[d]+pv[p]); S_p[p] = sum_d relu(dv[d]+pv[p])
__global__ void interact_kernel(const float* __restrict__ datt, const float* __restrict__ patt,
                                float* __restrict__ Sd, float* __restrict__ Sp)
{
    int k = blockIdx.x, b = blockIdx.y;
    int t = threadIdx.x;
    __shared__ float dvs[D3L];
    __shared__ float red[8][D3L];

    const float* dv = datt + ((size_t)b * C3 + k) * D3L;
    const float* pv = patt + ((size_t)b * C3 + k) * P3L;
    float* SpRow = Sp + ((size_t)b * C3 + k) * P3L;

    if (t < D3L) dvs[t] = dv[t];
    __syncthreads();

    float dl[D3L];
#pragma unroll
    for (int d = 0; d < D3L; d++) dl[d] = dvs[d];
    float sdp[D3L];
#pragma unroll
    for (int d = 0; d < D3L; d++) sdp[d] = 0.f;

    for (int p = t; p < P3L; p += 256) {
        float pvv = pv[p];
        float sp = 0.f;
#pragma unroll
        for (int d = 0; d < D3L; d++) {
            float v = fmaxf(dl[d] + pvv, 0.f);
            sdp[d] += v;
            sp += v;
        }
        SpRow[p] = sp;
    }

    int warp = t >> 5, lane = t & 31;
#pragma unroll
    for (int d = 0; d < D3L; d++) {
        float v = sdp[d];
        v += __shfl_xor_sync(0xffffffffu, v, 16);
        v += __shfl_xor_sync(0xffffffffu, v, 8);
        v += __shfl_xor_sync(0xffffffffu, v, 4);
        v += __shfl_xor_sync(0xffffffffu, v, 2);
        v += __shfl_xor_sync(0xffffffffu, v, 1);
        if (lane == 0) red[warp][d] = v;
    }
    __syncthreads();
    if (t < D3L) {
        float s = 0.f;
#pragma unroll
        for (int w = 0; w < 8; w++) s += red[w][t];
        Sd[((size_t)b * C3 + k) * D3L + t] = s;
    }
}

// pair[b][off+k] = max_l x[b][k][l] * (0.5 + att[b][k][l])
__global__ void pool_kernel(const float* __restrict__ x, const float* __restrict__ att,
                            float* __restrict__ pairv, int L, int off)
{
    int k = blockIdx.x, b = blockIdx.y;
    const float* xr = x + ((size_t)b * C3 + k) * L;
    const float* ar = att + ((size_t)b * C3 + k) * L;
    float m = -1e30f;
    for (int l = threadIdx.x; l < L; l += 32)
        m = fmaxf(m, xr[l] * (0.5f + ar[l]));
#pragma unroll
    for (int s = 16; s; s >>= 1)
        m = fmaxf(m, __shfl_xor_sync(0xffffffffu, m, s));
    if (threadIdx.x == 0) pairv[b * 320 + off + k] = m;
}

__global__ void fc_kernel(const float* __restrict__ x, const float* __restrict__ W,
                          const float* __restrict__ bias, float* __restrict__ y,
                          int IN, int OUT, int leaky)
{
    int b = blockIdx.y;
    int o = blockIdx.x * blockDim.x + threadIdx.x;
    if (o >= OUT) return;
    const float4* xb = (const float4*)(x + (size_t)b * IN);
    const float4* Wo = (const float4*)(W + (size_t)o * IN);
    float acc = bias[o];
    int n4 = IN >> 2;
#pragma unroll 4
    for (int i = 0; i < n4; i++) {
        float4 xv = xb[i], wv = Wo[i];
        acc = fmaf(wv.x, xv.x, acc);
        acc = fmaf(wv.y, xv.y, acc);
        acc = fmaf(wv.z, xv.z, acc);
        acc = fmaf(wv.w, xv.w, acc);
    }
    if (leaky) acc = acc > 0.f ? acc : 0.01f * acc;
    y[(size_t)b * OUT + o] = acc;
}

// ---------------- launch ----------------
extern "C" void kernel_launch(void* const* d_in, const int* in_sizes, int n_in,
                              void* d_out, int out_size)
{
    const int*   dtok = (const int*)d_in[0];
    const int*   ptok = (const int*)d_in[1];
    const float* demb = (const float*)d_in[2];
    const float* pemb = (const float*)d_in[3];
    const float* dW1 = (const float*)d_in[4],  *db1 = (const float*)d_in[5];
    const float* dW2 = (const float*)d_in[6],  *db2 = (const float*)d_in[7];
    const float* dW3 = (const float*)d_in[8],  *db3 = (const float*)d_in[9];
    const float* pW1 = (const float*)d_in[10], *pb1 = (const float*)d_in[11];
    const float* pW2 = (const float*)d_in[12], *pb2 = (const float*)d_in[13];
    const float* pW3 = (const float*)d_in[14], *pb3 = (const float*)d_in[15];
    const float* dattW = (const float*)d_in[16], *dattb = (const float*)d_in[17];
    const float* pattW = (const float*)d_in[18], *pattb = (const float*)d_in[19];
    const float* attW  = (const float*)d_in[20], *attb  = (const float*)d_in[21];
    const float* fc1W = (const float*)d_in[22], *fc1b = (const float*)d_in[23];
    const float* fc2W = (const float*)d_in[24], *fc2b = (const float*)d_in[25];
    const float* fc3W = (const float*)d_in[26], *fc3b = (const float*)d_in[27];
    const float* outW = (const float*)d_in[28], *outb = (const float*)d_in[29];
    float* out = (float*)d_out;

    float *de, *pe, *d1, *d2, *dc, *p1, *p2, *pc;
    float *datt, *patt, *Sd, *Sp, *catte, *patte, *pairv, *h1, *h2, *h3;
    cudaGetSymbolAddress((void**)&de, g_de);
    cudaGetSymbolAddress((void**)&pe, g_pe);
    cudaGetSymbolAddress((void**)&d1, g_d1);
    cudaGetSymbolAddress((void**)&d2, g_d2);
    cudaGetSymbolAddress((void**)&dc, g_dc);
    cudaGetSymbolAddress((void**)&p1, g_p1);
    cudaGetSymbolAddress((void**)&p2, g_p2);
    cudaGetSymbolAddress((void**)&pc, g_pc);
    cudaGetSymbolAddress((void**)&datt, g_datt);
    cudaGetSymbolAddress((void**)&patt, g_patt);
    cudaGetSymbolAddress((void**)&Sd, g_Sd);
    cudaGetSymbolAddress((void**)&Sp, g_Sp);
    cudaGetSymbolAddress((void**)&catte, g_catte);
    cudaGetSymbolAddress((void**)&patte, g_patte);
    cudaGetSymbolAddress((void**)&pairv, g_pair);
    cudaGetSymbolAddress((void**)&h1, g_h1);
    cudaGetSymbolAddress((void**)&h2, g_h2);
    cudaGetSymbolAddress((void**)&h3, g_h3);

    // embeddings
    embed_kernel<<<dim3((64 * DLEN + 255) / 256, NB), 256>>>(dtok, demb, de, DLEN);
    embed_kernel<<<dim3((64 * PLEN + 255) / 256, NB), 256>>>(ptok, pemb, pe, PLEN);

    // drug CNN stack (TILE_L=64 -> LT=16)
    conv_t<4, 64, 16, 64, 8, 0><<<dim3(1, C1 / 8, NB), 32>>>(de, dW1, db1, d1, DLEN, D1L, C1, 0.f);
    conv_t<6, 40, 20, 64, 16, 0><<<dim3(1, C2 / 16, NB), 64>>>(d1, dW2, db2, d2, D1L, D2L, C2, 0.f);
    conv_t<8, 80, 16, 64, 16, 0><<<dim3(1, C3 / 16, NB), 64>>>(d2, dW3, db3, dc, D2L, D3L, C3, 0.f);

    // protein CNN stack (TILE_L=256 -> LT=64)
    conv_t<4, 64, 16, 256, 8, 0><<<dim3(5, C1 / 8, NB), 128>>>(pe, pW1, pb1, p1, PLEN, P1L, C1, 0.f);
    conv_t<8, 40, 20, 256, 16, 0><<<dim3(5, C2 / 16, NB), 256>>>(p1, pW2, pb2, p2, P1L, P2L, C2, 0.f);
    conv_t<12, 80, 16, 256, 16, 0><<<dim3(5, C3 / 16, NB), 256>>>(p2, pW3, pb3, pc, P2L, P3L, C3, 0.f);

    // per-token attention projections (K=1 GEMM)
    conv_t<1, 160, 32, 64, 16, 1><<<dim3(1, C3 / 16, NB), 64>>>(dc, dattW, dattb, datt, D3L, D3L, C3, 0.f);
    conv_t<1, 160, 32, 256, 16, 1><<<dim3(5, C3 / 16, NB), 256>>>(pc, pattW, pattb, patt, P3L, P3L, C3, 0.f);

    // interaction sums (mean commuted past linear attW projection)
    interact_kernel<<<dim3(C3, NB), 256>>>(datt, patt, Sd, Sp);

    // attention outputs: sigmoid((S/N) @ attW^T + attb)
    conv_t<1, 160, 32, 64, 16, 2><<<dim3(1, C3 / 16, NB), 64>>>(Sd, attW, attb, catte, D3L, D3L, C3, 1.f / (float)P3L);
    conv_t<1, 160, 32, 256, 16, 2><<<dim3(5, C3 / 16, NB), 256>>>(Sp, attW, attb, patte, P3L, P3L, C3, 1.f / (float)D3L);

    // gated global max pool -> pair[b][320]
    pool_kernel<<<dim3(C3, NB), 32>>>(dc, catte, pairv, D3L, 0);
    pool_kernel<<<dim3(C3, NB), 32>>>(pc, patte, pairv, P3L, 160);

    // MLP head
    fc_kernel<<<dim3(4, NB), 256>>>(pairv, fc1W, fc1b, h1, 320, 1024, 1);
    fc_kernel<<<dim3(4, NB), 256>>>(h1, fc2W, fc2b, h2, 1024, 1024, 1);
    fc_kernel<<<dim3(2, NB), 256>>>(h2, fc3W, fc3b, h3, 1024, 512, 1);
    fc_kernel<<<dim3(1, NB), 32>>>(h3, outW, outb, out, 512, 2, 0);
}